// round 15
// baseline (speedup 1.0000x reference)
#include <cuda_runtime.h>

#define FULL 0xffffffffu
typedef unsigned long long u64;

constexpr int NW = 8;     // warps per block
constexpr int SPW = 8;    // samples per warp
constexpr int PAIRS = SPW / 2;

// interleaved per-warp activation region (floats); elem (…,k,p) at 2k+p
constexpr int FSP2 = 0;     // factors  6 rows x16 (12 used)          96
constexpr int AU2  = 96;    // u / h2   6 rows x68 (64 used)          408
constexpr int AV2  = 504;   // v        6 rows x68; ANF2 overlays     408
constexpr int ANF2 = 504;   // h1 / s1 (overlay of AV2)
constexpr int ADJ2 = 912;   // adjacency 6 rows x16                   96
constexpr int ASP2 = 1008;  // structured / pred 6 rows x16           96
constexpr int ACT2 = 1104;

__device__ __forceinline__ float sigm(float x) { return 1.0f / (1.0f + __expf(-x)); }

__device__ __forceinline__ float wsum16(float t) {
#pragma unroll
    for (int o = 8; o; o >>= 1) t += __shfl_xor_sync(FULL, t, o);
    return t;
}

__device__ __forceinline__ u64 pack2(float a, float b) {
    u64 r; asm("mov.b64 %0, {%1, %2};" : "=l"(r) : "f"(a), "f"(b)); return r;
}
__device__ __forceinline__ void unpack2(u64 v, float& a, float& b) {
    asm("mov.b64 {%0, %1}, %2;" : "=f"(a), "=f"(b) : "l"(v));
}
__device__ __forceinline__ u64 fma2(u64 a, u64 b, u64 c) {
    u64 d; asm("fma.rn.f32x2 %0, %1, %2, %3;" : "=l"(d) : "l"(a), "l"(b), "l"(c)); return d;
}
__device__ __forceinline__ u64 add2(u64 a, u64 b) {
    u64 d; asm("add.rn.f32x2 %0, %1, %2;" : "=l"(d) : "l"(a), "l"(b)); return d;
}

#define LD4(arr, dst, off)                                        \
    { float4 _a = *(const float4*)&(arr)[off];                    \
      (dst)[0] = _a.x; (dst)[1] = _a.y; (dst)[2] = _a.z; (dst)[3] = _a.w; }

__global__ __launch_bounds__(NW * 32, 4) void cad_kernel(
    const float* __restrict__ factors,
    const float* __restrict__ Wn,  const float* __restrict__ bn,
    const float* __restrict__ We1, const float* __restrict__ be1,
    const float* __restrict__ We2, const float* __restrict__ be2,
    const float* __restrict__ Wd1, const float* __restrict__ bd1,
    const float* __restrict__ Wd2, const float* __restrict__ bd2,
    const float* __restrict__ Wd3, const float* __restrict__ bd3,
    const float* __restrict__ Ws1, const float* __restrict__ bs1,
    const float* __restrict__ Ws2, const float* __restrict__ bs2,
    const float* __restrict__ Ws3, const float* __restrict__ bs3,
    float* __restrict__ out, int Btot)
{
    __shared__ __align__(16) float WuS[192], WvS[192];
    __shared__ __align__(16) float wd1S[192];
    __shared__ __align__(16) float buS[32], bvS[32];
    __shared__ __align__(16) float wd2T[32 * 36];
    __shared__ __align__(16) float wd3F[6 * 36];
    __shared__ __align__(16) float ws1T[32 * 20];
    __shared__ __align__(16) float ws2T[16 * 36];
    __shared__ __align__(16) float we2S[32];
    __shared__ float bd1S[32], bd2S[32], bs1S[32];
    __shared__ float bs2S[16], ws3S[16], bd3S[8], scal[2];
    __shared__ __align__(16) float act[NW][ACT2];

    const int tid = threadIdx.x;

    // ---- composed edge weights: Wu = Wn@We1[:32], Wv = Wn@We1[32:] ----
    if (tid < 192) {
        int f = tid >> 5, h = tid & 31;
        float au = 0.0f, av = 0.0f;
#pragma unroll 4
        for (int k = 0; k < 32; k++) {
            float wn = Wn[f * 32 + k];
            au = fmaf(wn, We1[k * 32 + h], au);
            av = fmaf(wn, We1[(32 + k) * 32 + h], av);
        }
        WuS[f * 32 + h] = au;
        WvS[f * 32 + h] = av;
        wd1S[f * 32 + h] = Wd1[f * 32 + h];
    }
    if (tid < 32) {
        float bu = be1[tid], bv = 0.0f;
#pragma unroll 4
        for (int k = 0; k < 32; k++) {
            float b = bn[k];
            bu = fmaf(b, We1[k * 32 + tid], bu);
            bv = fmaf(b, We1[(32 + k) * 32 + tid], bv);
        }
        buS[tid] = bu; bvS[tid] = bv;
    }
    for (int idx = tid; idx < 1024; idx += NW * 32) {
        int k = idx >> 5, l = idx & 31;
        wd2T[l * 36 + k] = Wd2[idx];
    }
    for (int idx = tid; idx < 576; idx += NW * 32) {
        int k = idx >> 5, l = idx & 31;
        ws1T[l * 20 + k] = Ws1[idx];
    }
    for (int idx = tid; idx < 512; idx += NW * 32) {
        int k = idx >> 4, m = idx & 15;
        ws2T[m * 36 + k] = Ws2[idx];
    }
    for (int idx = tid; idx < 192; idx += NW * 32) {
        int k3 = idx / 6, f3 = idx - k3 * 6;
        wd3F[f3 * 36 + k3] = Wd3[idx];
    }
    if (tid < 32) {
        we2S[tid] = We2[tid];
        bd1S[tid] = bd1[tid]; bd2S[tid] = bd2[tid]; bs1S[tid] = bs1[tid];
    }
    if (tid < 16) { bs2S[tid] = bs2[tid]; ws3S[tid] = Ws3[tid]; }
    if (tid < 6)  { bd3S[tid] = bd3[tid]; }
    if (tid == 0) { scal[0] = be2[0]; scal[1] = bs3[0]; }
    __syncthreads();

    const int lane = tid & 31;
    const int w = tid >> 5;
    float* A = act[w];

    const int i1 = lane / 6, j1 = lane - i1 * 6;   // element e = lane
    const int j2 = (lane < 4) ? lane + 2 : 2;      // element 32+lane -> (5, j2)

    // adjacency 30-edge map (lanes 30,31 shadow lane 29; no stores)
    const int la = (lane < 30) ? lane : 29;
    const int ia = la / 5;
    const int jt = la - ia * 5;
    const int ja = jt + (jt >= ia ? 1 : 0);

    // pred leftover map: lanes 0..7 -> (p = lane>>2, e = 32 + (lane&3))
    const int pL = (lane >> 2) & 1;
    const int j2x = 2 + (lane & 3);

#pragma unroll 1
    for (int it = 0; it < PAIRS; it++) {
        const int b0 = ((blockIdx.x * NW + w) * SPW) + 2 * it;
        if (b0 < Btot) {
            const bool v1 = (b0 + 1) < Btot;

            // ---- stage factors (interleaved) ----
#pragma unroll
            for (int p = 0; p < 2; p++) {
                const float* fb = factors + (size_t)(p ? (v1 ? b0 + 1 : b0) : b0) * 36;
                A[FSP2 + i1 * 16 + 2 * j1 + p] = fb[lane];
                if (lane < 4) A[FSP2 + 5 * 16 + 2 * j2 + p] = fb[32 + lane];
            }
            __syncwarp();

            // ---- u,v packed (lane = hidden) ----
            {
                u64 wu2[6], wv2[6];
#pragma unroll
                for (int f = 0; f < 6; f++) {
                    float a = WuS[f * 32 + lane]; wu2[f] = pack2(a, a);
                    float b = WvS[f * 32 + lane]; wv2[f] = pack2(b, b);
                }
                float bu = buS[lane], bv = bvS[lane];
                u64 bu2 = pack2(bu, bu), bv2 = pack2(bv, bv);
#pragma unroll
                for (int i = 0; i < 6; i++) {
                    ulonglong2 q0 = *(const ulonglong2*)&A[FSP2 + i * 16];
                    ulonglong2 q1 = *(const ulonglong2*)&A[FSP2 + i * 16 + 4];
                    ulonglong2 q2 = *(const ulonglong2*)&A[FSP2 + i * 16 + 8];
                    u64 u2 = bu2, v2 = bv2;
                    u2 = fma2(q0.x, wu2[0], u2); v2 = fma2(q0.x, wv2[0], v2);
                    u2 = fma2(q0.y, wu2[1], u2); v2 = fma2(q0.y, wv2[1], v2);
                    u2 = fma2(q1.x, wu2[2], u2); v2 = fma2(q1.x, wv2[2], v2);
                    u2 = fma2(q1.y, wu2[3], u2); v2 = fma2(q1.y, wv2[3], v2);
                    u2 = fma2(q2.x, wu2[4], u2); v2 = fma2(q2.x, wv2[4], v2);
                    u2 = fma2(q2.y, wu2[5], u2); v2 = fma2(q2.y, wv2[5], v2);
                    *(u64*)&A[AU2 + i * 68 + 2 * lane] = u2;
                    *(u64*)&A[AV2 + i * 68 + 2 * lane] = v2;
                }
            }
            __syncwarp();

            // ---- adjacency (lane = edge, scalar math on interleaved data) ----
            {
                float acc0 = 0.0f, acc1 = 0.0f;
#pragma unroll
                for (int tt = 0; tt < 8; tt++) {
                    float4 wq = *(const float4*)&we2S[4 * tt];
                    float4 uA = *(const float4*)&A[AU2 + ia * 68 + 8 * tt];
                    float4 vA = *(const float4*)&A[AV2 + ja * 68 + 8 * tt];
                    float4 uB = *(const float4*)&A[AU2 + ia * 68 + 8 * tt + 4];
                    float4 vB = *(const float4*)&A[AV2 + ja * 68 + 8 * tt + 4];
                    acc0 = fmaf(fmaxf(uA.x + vA.x, 0.0f), wq.x, acc0);
                    acc1 = fmaf(fmaxf(uA.y + vA.y, 0.0f), wq.x, acc1);
                    acc0 = fmaf(fmaxf(uA.z + vA.z, 0.0f), wq.y, acc0);
                    acc1 = fmaf(fmaxf(uA.w + vA.w, 0.0f), wq.y, acc1);
                    acc0 = fmaf(fmaxf(uB.x + vB.x, 0.0f), wq.z, acc0);
                    acc1 = fmaf(fmaxf(uB.y + vB.y, 0.0f), wq.z, acc1);
                    acc0 = fmaf(fmaxf(uB.z + vB.z, 0.0f), wq.w, acc0);
                    acc1 = fmaf(fmaxf(uB.w + vB.w, 0.0f), wq.w, acc1);
                }
                float be2v = scal[0];
                float a0 = sigm(acc0 + be2v), a1 = sigm(acc1 + be2v);
                if (lane < 30) *(u64*)&A[ADJ2 + ia * 16 + 2 * ja] = pack2(a0, a1);
                if (lane < 6)  *(u64*)&A[ADJ2 + lane * 16 + 2 * lane] = 0ull;  // diag
            }
            __syncwarp();

            // ---- coalesced adj gmem output ----
#pragma unroll
            for (int p = 0; p < 2; p++) {
                if (p == 0 || v1) {
                    float* oa = out + (size_t)(b0 + p) * 36;
                    oa[lane] = A[ADJ2 + i1 * 16 + 2 * j1 + p];
                    if (lane < 4) oa[32 + lane] = A[ADJ2 + 5 * 16 + 2 * j2 + p];
                }
            }

            // ---- structured packed (lane = (n=i1, i=j1)) ----
            {
                ulonglong2 aq0 = *(const ulonglong2*)&A[ADJ2 + j1 * 16];
                ulonglong2 aq1 = *(const ulonglong2*)&A[ADJ2 + j1 * 16 + 4];
                ulonglong2 aq2 = *(const ulonglong2*)&A[ADJ2 + j1 * 16 + 8];
                ulonglong2 fq0 = *(const ulonglong2*)&A[FSP2 + i1 * 16];
                ulonglong2 fq1 = *(const ulonglong2*)&A[FSP2 + i1 * 16 + 4];
                ulonglong2 fq2 = *(const ulonglong2*)&A[FSP2 + i1 * 16 + 8];
                u64 sv2 = fma2(aq0.x, fq0.x, 0ull);
                sv2 = fma2(aq0.y, fq0.y, sv2);
                sv2 = fma2(aq1.x, fq1.x, sv2);
                sv2 = fma2(aq1.y, fq1.y, sv2);
                sv2 = fma2(aq2.x, fq2.x, sv2);
                sv2 = fma2(aq2.y, fq2.y, sv2);
                *(u64*)&A[ASP2 + i1 * 16 + 2 * j1] = sv2;
                if (lane < 4) {
                    ulonglong2 bq0 = *(const ulonglong2*)&A[ADJ2 + j2 * 16];
                    ulonglong2 bq1 = *(const ulonglong2*)&A[ADJ2 + j2 * 16 + 4];
                    ulonglong2 bq2 = *(const ulonglong2*)&A[ADJ2 + j2 * 16 + 8];
                    ulonglong2 gq0 = *(const ulonglong2*)&A[FSP2 + 5 * 16];
                    ulonglong2 gq1 = *(const ulonglong2*)&A[FSP2 + 5 * 16 + 4];
                    ulonglong2 gq2 = *(const ulonglong2*)&A[FSP2 + 5 * 16 + 8];
                    u64 t2 = fma2(bq0.x, gq0.x, 0ull);
                    t2 = fma2(bq0.y, gq0.y, t2);
                    t2 = fma2(bq1.x, gq1.x, t2);
                    t2 = fma2(bq1.y, gq1.y, t2);
                    t2 = fma2(bq2.x, gq2.x, t2);
                    t2 = fma2(bq2.y, gq2.y, t2);
                    *(u64*)&A[ASP2 + 5 * 16 + 2 * j2] = t2;
                }
            }
            __syncwarp();

            // ---- h1 packed (lane = hidden) ----
            {
                u64 wd12[6];
#pragma unroll
                for (int f = 0; f < 6; f++) {
                    float a = wd1S[f * 32 + lane]; wd12[f] = pack2(a, a);
                }
                float bl = bd1S[lane];
                u64 bd12 = pack2(bl, bl);
#pragma unroll
                for (int n = 0; n < 6; n++) {
                    ulonglong2 s0 = *(const ulonglong2*)&A[ASP2 + n * 16];
                    ulonglong2 s1 = *(const ulonglong2*)&A[ASP2 + n * 16 + 4];
                    ulonglong2 s2 = *(const ulonglong2*)&A[ASP2 + n * 16 + 8];
                    u64 a2 = bd12;
                    a2 = fma2(s0.x, wd12[0], a2); a2 = fma2(s0.y, wd12[1], a2);
                    a2 = fma2(s1.x, wd12[2], a2); a2 = fma2(s1.y, wd12[3], a2);
                    a2 = fma2(s2.x, wd12[4], a2); a2 = fma2(s2.y, wd12[5], a2);
                    float lo, hi; unpack2(a2, lo, hi);
                    *(u64*)&A[ANF2 + n * 68 + 2 * lane] =
                        pack2(fmaxf(lo, 0.0f), fmaxf(hi, 0.0f));
                }
            }
            __syncwarp();

            // ---- h2 packed interchanged ----
            {
                u64 acc2[6];
                float bl = bd2S[lane];
                u64 b2 = pack2(bl, bl);
#pragma unroll
                for (int n = 0; n < 6; n++) acc2[n] = b2;
#pragma unroll
                for (int t = 0; t < 8; t++) {
                    float4 wq = *(const float4*)&wd2T[lane * 36 + 4 * t];
                    u64 w0 = pack2(wq.x, wq.x), w1 = pack2(wq.y, wq.y);
                    u64 w2p = pack2(wq.z, wq.z), w3 = pack2(wq.w, wq.w);
#pragma unroll
                    for (int n = 0; n < 6; n++) {
                        ulonglong2 hA = *(const ulonglong2*)&A[ANF2 + n * 68 + 8 * t];
                        ulonglong2 hB = *(const ulonglong2*)&A[ANF2 + n * 68 + 8 * t + 4];
                        acc2[n] = fma2(hA.x, w0, acc2[n]);
                        acc2[n] = fma2(hA.y, w1, acc2[n]);
                        acc2[n] = fma2(hB.x, w2p, acc2[n]);
                        acc2[n] = fma2(hB.y, w3, acc2[n]);
                    }
                }
#pragma unroll
                for (int n = 0; n < 6; n++) {
                    float lo, hi; unpack2(acc2[n], lo, hi);
                    *(u64*)&A[AU2 + n * 68 + 2 * lane] =
                        pack2(fmaxf(lo, 0.0f), fmaxf(hi, 0.0f));
                }
            }
            __syncwarp();

            // ---- pred packed + scalar leftover ----
            {
                u64 pacc = 0ull;
                float pbx = 0.0f;
#pragma unroll
                for (int t = 0; t < 8; t++) {
                    float4 wq = *(const float4*)&wd3F[j1 * 36 + 4 * t];
                    u64 w0 = pack2(wq.x, wq.x), w1 = pack2(wq.y, wq.y);
                    u64 w2p = pack2(wq.z, wq.z), w3 = pack2(wq.w, wq.w);
                    ulonglong2 hA = *(const ulonglong2*)&A[AU2 + i1 * 68 + 8 * t];
                    ulonglong2 hB = *(const ulonglong2*)&A[AU2 + i1 * 68 + 8 * t + 4];
                    pacc = fma2(hA.x, w0, pacc);
                    pacc = fma2(hA.y, w1, pacc);
                    pacc = fma2(hB.x, w2p, pacc);
                    pacc = fma2(hB.y, w3, pacc);
                    // leftover: row 5, sample pL, cols j2x (all lanes compute; lanes<8 store)
                    float4 rA = *(const float4*)&A[AU2 + 5 * 68 + 8 * t];
                    float4 rB = *(const float4*)&A[AU2 + 5 * 68 + 8 * t + 4];
                    float4 wx = *(const float4*)&wd3F[j2x * 36 + 4 * t];
                    float h0 = pL ? rA.y : rA.x;
                    float h1v = pL ? rA.w : rA.z;
                    float h2v = pL ? rB.y : rB.x;
                    float h3v = pL ? rB.w : rB.z;
                    pbx = fmaf(h0, wx.x, pbx);
                    pbx = fmaf(h1v, wx.y, pbx);
                    pbx = fmaf(h2v, wx.z, pbx);
                    pbx = fmaf(h3v, wx.w, pbx);
                }
                float b3 = bd3S[j1];
                u64 pr2 = add2(pacc, pack2(b3, b3));
                *(u64*)&A[ASP2 + i1 * 16 + 2 * j1] = pr2;
                float pp0, pp1; unpack2(pr2, pp0, pp1);
                {
                    float* op0 = out + (size_t)Btot * 36 + (size_t)b0 * 36;
                    op0[lane] = pp0;
                    if (v1) (op0 + 36)[lane] = pp1;
                }
                if (lane < 8) {
                    float pv = pbx + bd3S[j2x];
                    A[ASP2 + 5 * 16 + 2 * j2x + pL] = pv;
                    if (pL == 0 || v1)
                        out[(size_t)Btot * 36 + (size_t)(b0 + pL) * 36 + 32 + (lane & 3)] = pv;
                }
            }
            __syncwarp();

            // ---- scorer layer 1 (scalar math, interleaved reads) ----
            {
                float ws1c[18];
#pragma unroll
                for (int t = 0; t < 4; t++) LD4(ws1T, ws1c + 4 * t, lane * 20 + 4 * t);
                {
                    float2 a = *(const float2*)&ws1T[lane * 20 + 16];
                    ws1c[16] = a.x; ws1c[17] = a.y;
                }
                float bs1l = bs1S[lane];
#pragma unroll
                for (int n = 0; n < 6; n++) {
                    float4 fA = *(const float4*)&A[FSP2 + n * 16];
                    float4 fB = *(const float4*)&A[FSP2 + n * 16 + 4];
                    float4 fC = *(const float4*)&A[FSP2 + n * 16 + 8];
                    float4 pA = *(const float4*)&A[ASP2 + n * 16];
                    float4 pB = *(const float4*)&A[ASP2 + n * 16 + 4];
                    float4 pC = *(const float4*)&A[ASP2 + n * 16 + 8];
                    float fk0[6] = {fA.x, fA.z, fB.x, fB.z, fC.x, fC.z};
                    float fk1[6] = {fA.y, fA.w, fB.y, fB.w, fC.y, fC.w};
                    float pk0[6] = {pA.x, pA.z, pB.x, pB.z, pC.x, pC.z};
                    float pk1[6] = {pA.y, pA.w, pB.y, pB.w, pC.y, pC.w};
                    float acc0 = bs1l, acc1 = bs1l;
#pragma unroll
                    for (int k = 0; k < 6; k++) {
                        acc0 = fmaf(fk0[k], ws1c[k], acc0);
                        acc0 = fmaf(pk0[k], ws1c[6 + k], acc0);
                        acc0 = fmaf(fabsf(fk0[k] - pk0[k]), ws1c[12 + k], acc0);
                        acc1 = fmaf(fk1[k], ws1c[k], acc1);
                        acc1 = fmaf(pk1[k], ws1c[6 + k], acc1);
                        acc1 = fmaf(fabsf(fk1[k] - pk1[k]), ws1c[12 + k], acc1);
                    }
                    *(u64*)&A[ANF2 + n * 68 + 2 * lane] =
                        pack2(fmaxf(acc0, 0.0f), fmaxf(acc1, 0.0f));
                }
            }
            __syncwarp();

            // ---- scorer layers 2+3 packed ----
            {
                u64 acc2[6];
                float bl = bs2S[lane & 15];
                u64 b2 = pack2(bl, bl);
#pragma unroll
                for (int n = 0; n < 6; n++) acc2[n] = b2;
#pragma unroll
                for (int t = 0; t < 8; t++) {
                    float4 wq = *(const float4*)&ws2T[(lane & 15) * 36 + 4 * t];
                    u64 w0 = pack2(wq.x, wq.x), w1 = pack2(wq.y, wq.y);
                    u64 w2p = pack2(wq.z, wq.z), w3 = pack2(wq.w, wq.w);
#pragma unroll
                    for (int n = 0; n < 6; n++) {
                        ulonglong2 sA = *(const ulonglong2*)&A[ANF2 + n * 68 + 8 * t];
                        ulonglong2 sB = *(const ulonglong2*)&A[ANF2 + n * 68 + 8 * t + 4];
                        acc2[n] = fma2(sA.x, w0, acc2[n]);
                        acc2[n] = fma2(sA.y, w1, acc2[n]);
                        acc2[n] = fma2(sB.x, w2p, acc2[n]);
                        acc2[n] = fma2(sB.y, w3, acc2[n]);
                    }
                }
                float ws3l = (lane < 16) ? ws3S[lane] : 0.0f;
                float bs3v = scal[1];
                float ssum0 = 0.0f, ssum1 = 0.0f;
#pragma unroll
                for (int n = 0; n < 6; n++) {
                    float lo, hi; unpack2(acc2[n], lo, hi);
                    float t0 = fmaxf(lo, 0.0f) * ws3l;   // lanes >= 16: 0
                    float t1 = fmaxf(hi, 0.0f) * ws3l;
                    ssum0 += sigm(wsum16(t0) + bs3v);
                    ssum1 += sigm(wsum16(t1) + bs3v);
                }
                if (lane == 0) {
                    out[(size_t)Btot * 72 + b0] = ssum0 * (1.0f / 6.0f);
                    if (v1) out[(size_t)Btot * 72 + b0 + 1] = ssum1 * (1.0f / 6.0f);
                }
            }
            __syncwarp();
        }
    }
}

extern "C" void kernel_launch(void* const* d_in, const int* in_sizes, int n_in,
                              void* d_out, int out_size) {
    const float* p[19];
    for (int i = 0; i < 19; i++) p[i] = (const float*)d_in[i];
    int Btot = in_sizes[0] / 36;
    int per_block = NW * SPW;
    int blocks = (Btot + per_block - 1) / per_block;
    cad_kernel<<<blocks, NW * 32>>>(
        p[0], p[1], p[2], p[3], p[4], p[5], p[6], p[7], p[8], p[9], p[10],
        p[11], p[12], p[13], p[14], p[15], p[16], p[17], p[18],
        (float*)d_out, Btot);
}